// round 13
// baseline (speedup 1.0000x reference)
#include <cuda_runtime.h>
#include <cuda_bf16.h>
#include <math.h>
#include <stdint.h>

#define BB   256
#define TT   365
#define HH   512
#define DD   32
#define K3   1536
#define DS   27
#define NBLK 128
#define KTOT 544

// ---------------- persistent device state ----------------
// Weight staging: row P = nt*96 + g*32 + ul, k in [0,544) = [x(32) ; h(512)]
__device__ __align__(16) __nv_bfloat16 g_Wp_hi[K3 * KTOT];
__device__ __align__(16) __nv_bfloat16 g_Wp_lo[K3 * KTOT];
__device__ __align__(16) __nv_bfloat16 g_x_hi[BB * TT * DD];
__device__ __align__(16) __nv_bfloat16 g_x_lo[BB * TT * DD];
__device__ __align__(16) __nv_bfloat16 g_h_hi[2][BB * HH];
__device__ __align__(16) __nv_bfloat16 g_h_lo[2][BB * HH];
__device__ unsigned g_grp_cnt[8 * 32];      // 128B stride per mt-group
__device__ unsigned g_grp_phase[8 * 32];

__device__ __forceinline__ float hsig(float x) {
    return fminf(fmaxf(0.2f * x + 0.5f, 0.0f), 1.0f);
}
__device__ __forceinline__ float ftanh(float x) {
    float t = __expf(-2.0f * fabsf(x));
    return copysignf(__fdividef(1.0f - t, 1.0f + t), x);
}
__device__ __forceinline__ uint32_t smem_u32(const void* p) {
    uint32_t a;
    asm("{ .reg .u64 t; cvta.to.shared.u64 t, %1; cvt.u32.u64 %0, t; }" : "=r"(a) : "l"(p));
    return a;
}

#define LDSM_X4(r0, r1, r2, r3, addr)                                          \
    asm volatile("ldmatrix.sync.aligned.m8n8.x4.shared.b16 {%0,%1,%2,%3}, [%4];" \
                 : "=r"(r0), "=r"(r1), "=r"(r2), "=r"(r3) : "r"(addr))

#define MMA_BF16(d, a0, a1, a2, a3, b0, b1)                                    \
    asm volatile("mma.sync.aligned.m16n8k16.row.col.f32.bf16.bf16.f32 "        \
                 "{%0,%1,%2,%3}, {%4,%5,%6,%7}, {%8,%9}, {%0,%1,%2,%3};"       \
                 : "+f"((d)[0]), "+f"((d)[1]), "+f"((d)[2]), "+f"((d)[3])      \
                 : "r"(a0), "r"(a1), "r"(a2), "r"(a3), "r"(b0), "r"(b1))

#define CP_ASYNC(dst, src, sz) \
    asm volatile("cp.async.cg.shared.global [%0], [%1], 16, %2;" \
                 :: "r"(dst), "l"(src), "r"(sz))
#define CP_COMMIT() asm volatile("cp.async.commit_group;" ::: "memory")
#define CP_WAIT0()  asm volatile("cp.async.wait_group 0;" ::: "memory")
#define CP_WAIT1()  asm volatile("cp.async.wait_group 1;" ::: "memory")
#define CP_WAIT2()  asm volatile("cp.async.wait_group 2;" ::: "memory")

// ---------------- SMEM layout ----------------
#define BROW      1104            // 544*2 + 16B pad
#define SM_BHI    0
#define SM_BLO    105984
#define SM_A      211968          // 4 slab bufs x 4096 (swizzled); red = bufs 1-3
#define ABUF_SZ   4096
#define SMEM_TOTAL 228352

// ---------------- prep kernels ----------------
__global__ void reset_bar() {
    if (threadIdx.x < 8 * 32) {
        g_grp_cnt[threadIdx.x] = 0;
        g_grp_phase[threadIdx.x] = 0;
    }
}

__global__ void prep_weights(const float* __restrict__ Wx, const float* __restrict__ Wh) {
    int P = blockIdx.x;                 // P = nt*96 + g*32 + ul
    int nt = P / 96, rq = P - nt * 96;
    int g = rq >> 5, ul = rq & 31;
    int col = g * HH + nt * 32 + ul;
    for (int k = threadIdx.x; k < KTOT; k += blockDim.x) {
        float w = (k < DD) ? Wx[(size_t)k * K3 + col]
                           : Wh[(size_t)(k - DD) * K3 + col];
        __nv_bfloat16 hi = __float2bfloat16(w);
        g_Wp_hi[(size_t)P * KTOT + k] = hi;
        g_Wp_lo[(size_t)P * KTOT + k] = __float2bfloat16(w - __bfloat162float(hi));
    }
}

__global__ void prep_x(const float* __restrict__ x_dyn) {
    int i = blockIdx.x * blockDim.x + threadIdx.x;
    if (i >= BB * TT * DD) return;
    float v = x_dyn[i];
    __nv_bfloat16 hi = __float2bfloat16(v);
    g_x_hi[i] = hi;
    g_x_lo[i] = __float2bfloat16(v - __bfloat162float(hi));
}

// ---------------- split group barrier (16 CTAs per mt) ----------------
// arrive: tid0 only, after a __syncthreads() covering this CTA's h writes.
__device__ __forceinline__ void grp_arrive(int mt, unsigned round) {
    unsigned old;
    asm volatile("atom.add.acq_rel.gpu.global.u32 %0, [%1], 1;"
                 : "=r"(old) : "l"(&g_grp_cnt[mt * 32]) : "memory");
    if (old + 1u == round * 16u)
        asm volatile("st.release.gpu.global.u32 [%0], %1;"
                     :: "l"(&g_grp_phase[mt * 32]), "r"(round) : "memory");
}
__device__ __forceinline__ void grp_wait(int mt, unsigned round) {
    if (threadIdx.x == 0) {
        unsigned p;
        do {
            asm volatile("ld.acquire.gpu.global.u32 %0, [%1];"
                         : "=r"(p) : "l"(&g_grp_phase[mt * 32]) : "memory");
        } while (p < round);
    }
    __syncthreads();
}

// ---- fragment bank load: 4 A LDSM + 3 B LDSM ----
#define LDSM_BANK(FA, FB, Ab_, Bb_)                                            \
    LDSM_X4(FA[0], FA[1], FA[2], FA[3], (Ab_));                                \
    LDSM_X4(FA[4], FA[5], FA[6], FA[7], (Ab_) + 1024);                         \
    LDSM_X4(FA[8], FA[9], FA[10], FA[11], (Ab_) + 2048);                       \
    LDSM_X4(FA[12], FA[13], FA[14], FA[15], (Ab_) + 3072);                     \
    LDSM_X4(FB[0], FB[1], FB[2], FB[3], bA + (Bb_));                           \
    LDSM_X4(FB[4], FB[5], FB[6], FB[7], bB + (Bb_));                           \
    LDSM_X4(FB[8], FB[9], FB[10], FB[11], bC + (Bb_));

// ---- 18 compensated MMAs on one bank ----
#define MMA_BANK(FA, FB)                                                       \
    MMA_BF16(acc[0][0], FA[0], FA[1], FA[2], FA[3], FB[0], FB[1]);             \
    MMA_BF16(acc[0][1], FA[4], FA[5], FA[6], FA[7], FB[0], FB[1]);             \
    MMA_BF16(acc[1][0], FA[0], FA[1], FA[2], FA[3], FB[2], FB[3]);             \
    MMA_BF16(acc[1][1], FA[4], FA[5], FA[6], FA[7], FB[2], FB[3]);             \
    MMA_BF16(acc[2][0], FA[0], FA[1], FA[2], FA[3], FB[4], FB[5]);             \
    MMA_BF16(acc[2][1], FA[4], FA[5], FA[6], FA[7], FB[4], FB[5]);             \
    MMA_BF16(acc[0][0], FA[0], FA[1], FA[2], FA[3], FB[6], FB[7]);             \
    MMA_BF16(acc[0][1], FA[4], FA[5], FA[6], FA[7], FB[6], FB[7]);             \
    MMA_BF16(acc[1][0], FA[0], FA[1], FA[2], FA[3], FB[8], FB[9]);             \
    MMA_BF16(acc[1][1], FA[4], FA[5], FA[6], FA[7], FB[8], FB[9]);             \
    MMA_BF16(acc[2][0], FA[0], FA[1], FA[2], FA[3], FB[10], FB[11]);           \
    MMA_BF16(acc[2][1], FA[4], FA[5], FA[6], FA[7], FB[10], FB[11]);           \
    MMA_BF16(acc[0][0], FA[8], FA[9], FA[10], FA[11], FB[0], FB[1]);           \
    MMA_BF16(acc[0][1], FA[12], FA[13], FA[14], FA[15], FB[0], FB[1]);         \
    MMA_BF16(acc[1][0], FA[8], FA[9], FA[10], FA[11], FB[2], FB[3]);           \
    MMA_BF16(acc[1][1], FA[12], FA[13], FA[14], FA[15], FB[2], FB[3]);         \
    MMA_BF16(acc[2][0], FA[8], FA[9], FA[10], FA[11], FB[4], FB[5]);           \
    MMA_BF16(acc[2][1], FA[12], FA[13], FA[14], FA[15], FB[4], FB[5]);

// One pipeline iteration (j = 1..16):
// wait slab j+1 landed -> sync -> issue slab j+4 (or next-step x at j=16)
// -> LDSM slab j+1 -> MMA slab j
#define STEP_ITER(J, FAc, FBc, FAn, FBn) do {                                  \
    if ((J) <= 13) { CP_WAIT2(); }                                             \
    else if ((J) == 14) { CP_WAIT1(); }                                        \
    else if ((J) == 15) { CP_WAIT0(); }                                        \
    __syncthreads();                                                           \
    if ((J) <= 12) {                                                           \
        CP_ASYNC(s0 + SM_A + (uint32_t)(((J) + 4) & 3) * ABUF_SZ + dst_off,    \
                 hsrc + hrow + ((uint32_t)((nt + (J) + 3) & 15) << 5), 16);    \
        CP_COMMIT();                                                           \
    }                                                                          \
    if ((J) == 16 && t + 1 < TT) {                                             \
        CP_ASYNC(s0 + SM_A + dst_off, xb + xsrc0 + (size_t)(t + 1) * DD, 16);  \
        CP_COMMIT();                                                           \
    }                                                                          \
    if ((J) < 16) {                                                            \
        const uint32_t Ab_ = s0 + SM_A + (uint32_t)(((J) + 1) & 3) * ABUF_SZ + a_off; \
        const uint32_t Bb_ = 64 + 64 * (uint32_t)((nt + (J)) & 15) + khoff;    \
        LDSM_BANK(FAn, FBn, Ab_, Bb_)                                          \
    }                                                                          \
    MMA_BANK(FAc, FBc)                                                         \
} while (0)

// ---------------- persistent LSTM kernel ----------------
// 128 CTAs x 256 thr. CTA tile 32 rows x 32 units (96 z-cols).
// K = 17 slabs of 32 (slab0 = x, slab j = h-block (nt+j-1)&15).
// Split barrier: arrive at end of epilogue; wait AFTER own-data slab0/1
// LDSM + slab0 MMA, so barrier skew hides under useful work.
__global__ __launch_bounds__(256, 1)
void lstm_persist(const float* __restrict__ x_static,
                  const float* __restrict__ sk,
                  const float* __restrict__ sb,
                  const float* __restrict__ bias,
                  float* __restrict__ out) {
    extern __shared__ char smem[];
    const uint32_t s0 = smem_u32(smem);
    const int tid = threadIdx.x;
    const int lane = tid & 31;
    const int wid = tid >> 5;
    const int nq = wid & 3;
    const int khalf = wid >> 2;
    const uint32_t khoff = (uint32_t)khalf * 32;
    const int mt = blockIdx.x & 7;
    const int nt = blockIdx.x >> 3;
    const int m0 = mt * 32;
    const int u0 = nt * 32;

    // ---- one-time: weights into SMEM ----
    for (int i = tid; i < 96 * 68; i += 256) {
        int pl = i / 68, c = i - pl * 68;
        size_t src = (size_t)(nt * 96 + pl) * KTOT + c * 8;
        *reinterpret_cast<uint4*>(smem + SM_BHI + pl * BROW + c * 16) =
            *reinterpret_cast<const uint4*>(&g_Wp_hi[src]);
        *reinterpret_cast<uint4*>(smem + SM_BLO + pl * BROW + c * 16) =
            *reinterpret_cast<const uint4*>(&g_Wp_lo[src]);
    }

    // ---- per-thread ownership (epilogue in khalf==0 warps) ----
    const int gr = m0 + (lane >> 2);
    const int uA = u0 + nq * 8 + (lane & 3) * 2;

    const float bf0 = bias[uA],          bf1 = bias[uA + 1];
    const float bg0 = bias[HH + uA],     bg1 = bias[HH + uA + 1];
    const float bo0 = bias[2 * HH + uA], bo1 = bias[2 * HH + uA + 1];

    float c_reg[8], ig_reg[8];
#pragma unroll
    for (int i = 0; i < 8; i++) c_reg[i] = 0.f;
    if (khalf == 0) {
#pragma unroll
        for (int i = 0; i < 4; i++) {
            int row = gr + i * 8;
#pragma unroll
            for (int jj = 0; jj < 2; jj++) {
                int u = uA + jj;
                float a = sb[u];
#pragma unroll
                for (int d = 0; d < DS; d++)
                    a = fmaf(x_static[row * DS + d], sk[d * HH + u], a);
                ig_reg[i * 2 + jj] = hsig(a);
            }
            __nv_bfloat162 z2; z2.x = __float2bfloat16(0.f); z2.y = z2.x;
            *reinterpret_cast<__nv_bfloat162*>(&g_h_hi[0][row * HH + uA]) = z2;
            *reinterpret_cast<__nv_bfloat162*>(&g_h_lo[0][row * HH + uA]) = z2;
        }
    }

    // ---- hoisted loader constants (1 cp.async per thread per slab) ----
    const int halfl = tid >> 7;                 // 0 hi, 1 lo
    const int rowl = (tid >> 2) & 31;
    const int ql = tid & 3;
    const uint32_t dst_off = halfl * 2048 + rowl * 64
                           + ((ql ^ ((rowl >> 1) & 3)) << 4);     // XOR swizzle
    const __nv_bfloat16* __restrict__ xb = halfl ? g_x_lo : g_x_hi;
    const size_t xsrc0 = (size_t)(m0 + rowl) * TT * DD + ql * 8;
    const uint32_t hrow = (m0 + rowl) * HH + ql * 8;              // + b*32

    // ---- ldmatrix lane addresses ----
    const uint32_t a_off = (lane & 15) * 64
        + ((((uint32_t)khalf * 2 + (lane >> 4)) ^ (((lane & 15) >> 1) & 3)) << 4);
    const int oct = lane >> 3, l8 = lane & 7;
    const uint32_t koff = (oct & 1) * 16;
    const int wq8 = nq * 8;
    const uint32_t bA = s0 + SM_BHI + ((oct < 2 ? wq8 : 32 + wq8) + l8) * BROW + koff;
    const uint32_t bB = (oct < 2 ? s0 + SM_BHI + (64 + wq8 + l8) * BROW
                                 : s0 + SM_BLO + (wq8 + l8) * BROW) + koff;
    const uint32_t bC = s0 + SM_BLO + ((oct < 2 ? 32 : 64) + wq8 + l8) * BROW + koff;

    // prologue: h(0) visible CTA-wide, issue slab0 (x t=0) + slab1 (own h),
    // then post arrival for round 1.
    __syncthreads();
    CP_ASYNC(s0 + SM_A + dst_off, xb + xsrc0, 16);
    CP_COMMIT();
    {
        const __nv_bfloat16* hb = halfl ? g_h_lo[0] : g_h_hi[0];
        CP_ASYNC(s0 + SM_A + ABUF_SZ + dst_off, hb + hrow + nt * 32, 16);
        CP_COMMIT();
    }
    if (tid == 0) grp_arrive(mt, 1u);

    uint32_t fA0[16], fB0[12], fA1[16], fB1[12];

#pragma unroll 1
    for (int t = 0; t < TT; t++) {
        const int tpar = t & 1;
        const __nv_bfloat16* __restrict__ hsrc =
            halfl ? g_h_lo[tpar] : g_h_hi[tpar];

        // ---- own-data pre-work (no inter-CTA dependency) ----
        CP_WAIT0();                 // slab0 (x) + slab1 (own h) landed
        __syncthreads();
        LDSM_BANK(fA0, fB0, s0 + SM_A + a_off, khoff)                       // slab0
        LDSM_BANK(fA1, fB1, s0 + SM_A + ABUF_SZ + a_off,
                  64 + 64 * (uint32_t)nt + khoff)                           // slab1

        float acc[3][2][4];
#pragma unroll
        for (int g = 0; g < 3; g++)
#pragma unroll
            for (int mf = 0; mf < 2; mf++)
#pragma unroll
                for (int e2 = 0; e2 < 4; e2++) acc[g][mf][e2] = 0.f;

        MMA_BANK(fA0, fB0)          // slab0 overlaps other CTAs' arrivals

        // ---- barrier wait (arrive was posted at end of previous step) ----
        grp_wait(mt, (unsigned)t + 1u);

        // issue slabs 2,3,4 (blocks nt+1, nt+2, nt+3); slab4 reuses buf0
        CP_ASYNC(s0 + SM_A + 2 * ABUF_SZ + dst_off,
                 hsrc + hrow + (((nt + 1) & 15) << 5), 16);
        CP_COMMIT();
        CP_ASYNC(s0 + SM_A + 3 * ABUF_SZ + dst_off,
                 hsrc + hrow + (((nt + 2) & 15) << 5), 16);
        CP_COMMIT();
        CP_ASYNC(s0 + SM_A + dst_off,
                 hsrc + hrow + (((nt + 3) & 15) << 5), 16);
        CP_COMMIT();

#pragma unroll 1
        for (int j = 1; j < 16; j += 2) {
            STEP_ITER(j,     fA1, fB1, fA0, fB0);
            STEP_ITER(j + 1, fA0, fB0, fA1, fB1);
        }

        // ---- cross-warp k reduction (red = slab bufs 1-3; no extra sync:
        // iter16 did no LDSM and only wrote buf0) ----
        float* red = reinterpret_cast<float*>(smem + SM_A + ABUF_SZ);
        if (khalf == 1) {
            int s = (wid - 4) * 32 + lane;
#pragma unroll
            for (int g = 0; g < 3; g++)
#pragma unroll
                for (int mf = 0; mf < 2; mf++)
#pragma unroll
                    for (int e2 = 0; e2 < 4; e2++)
                        red[(g * 8 + mf * 4 + e2) * 128 + s] = acc[g][mf][e2];
        }
        __syncthreads();

        if (khalf == 0) {
            int s = wid * 32 + lane;
#pragma unroll
            for (int g = 0; g < 3; g++)
#pragma unroll
                for (int mf = 0; mf < 2; mf++)
#pragma unroll
                    for (int e2 = 0; e2 < 4; e2++)
                        acc[g][mf][e2] += red[(g * 8 + mf * 4 + e2) * 128 + s];

            __nv_bfloat16* __restrict__ hdst_hi = g_h_hi[tpar ^ 1];
            __nv_bfloat16* __restrict__ hdst_lo = g_h_lo[tpar ^ 1];
#pragma unroll
            for (int i = 0; i < 4; i++) {
                const int mf = i >> 1, dp = (i & 1) * 2;
                float zf0 = acc[0][mf][dp + 0] + bf0, zf1 = acc[0][mf][dp + 1] + bf1;
                float zg0 = acc[1][mf][dp + 0] + bg0, zg1 = acc[1][mf][dp + 1] + bg1;
                float zo0 = acc[2][mf][dp + 0] + bo0, zo1 = acc[2][mf][dp + 1] + bo1;
                float c0 = hsig(zf0) * c_reg[i * 2 + 0] + ig_reg[i * 2 + 0] * ftanh(zg0);
                float c1 = hsig(zf1) * c_reg[i * 2 + 1] + ig_reg[i * 2 + 1] * ftanh(zg1);
                c_reg[i * 2 + 0] = c0;
                c_reg[i * 2 + 1] = c1;
                float h0 = hsig(zo0) * ftanh(c0);
                float h1 = hsig(zo1) * ftanh(c1);
                int row = gr + i * 8;
                int idx = row * HH + uA;
                __nv_bfloat16 b0 = __float2bfloat16(h0);
                __nv_bfloat16 b1 = __float2bfloat16(h1);
                __nv_bfloat162 ph; ph.x = b0; ph.y = b1;
                *reinterpret_cast<__nv_bfloat162*>(&hdst_hi[idx]) = ph;
                __nv_bfloat162 pl;
                pl.x = __float2bfloat16(h0 - __bfloat162float(b0));
                pl.y = __float2bfloat16(h1 - __bfloat162float(b1));
                *reinterpret_cast<__nv_bfloat162*>(&hdst_lo[idx]) = pl;
                float2 ov = make_float2(h0, h1);
                *reinterpret_cast<float2*>(&out[(size_t)row * TT * HH + (size_t)t * HH + uA]) = ov;
            }
        }

        __syncthreads();                 // red reads + h(t+1) writes done CTA-wide
        if (tid == 0) grp_arrive(mt, (unsigned)t + 2u);   // publish h(t+1)
        if (t + 1 < TT) {                // slab1-next (own h(t+1)); slab0-next
            const __nv_bfloat16* hb =    // was issued at iter16
                halfl ? g_h_lo[(t + 1) & 1] : g_h_hi[(t + 1) & 1];
            CP_ASYNC(s0 + SM_A + ABUF_SZ + dst_off, hb + hrow + nt * 32, 16);
            CP_COMMIT();
        }
    }
}

// ---------------- launcher ----------------
extern "C" void kernel_launch(void* const* d_in, const int* in_sizes, int n_in,
                              void* d_out, int out_size) {
    const float* x_dyn    = (const float*)d_in[0];
    const float* x_static = (const float*)d_in[1];
    const float* Wx       = (const float*)d_in[2];
    const float* Wh       = (const float*)d_in[3];
    const float* bias     = (const float*)d_in[4];
    const float* sk       = (const float*)d_in[5];
    const float* sb       = (const float*)d_in[6];
    float* out = (float*)d_out;

    cudaFuncSetAttribute(lstm_persist, cudaFuncAttributeMaxDynamicSharedMemorySize, SMEM_TOTAL);

    reset_bar<<<1, 256>>>();
    prep_weights<<<K3, 128>>>(Wx, Wh);
    prep_x<<<(BB * TT * DD + 127) / 128, 128>>>(x_dyn);
    lstm_persist<<<NBLK, 256, SMEM_TOTAL>>>(x_static, sk, sb, bias, out);
}

// round 14
// speedup vs baseline: 1.0683x; 1.0683x over previous
#include <cuda_runtime.h>
#include <cuda_bf16.h>
#include <math.h>
#include <stdint.h>

#define BB   256
#define TT   365
#define HH   512
#define DD   32
#define K3   1536
#define DS   27
#define NBLK 128
#define KTOT 544

// ---------------- persistent device state ----------------
// Weight staging: row P = nt*96 + g*32 + ul, k in [0,544) = [x(32) ; h(512)]
__device__ __align__(16) __nv_bfloat16 g_Wp_hi[K3 * KTOT];
__device__ __align__(16) __nv_bfloat16 g_Wp_lo[K3 * KTOT];
__device__ __align__(16) __nv_bfloat16 g_x_hi[BB * TT * DD];
__device__ __align__(16) __nv_bfloat16 g_x_lo[BB * TT * DD];
__device__ __align__(16) __nv_bfloat16 g_h_hi[2][BB * HH];
__device__ __align__(16) __nv_bfloat16 g_h_lo[2][BB * HH];
__device__ unsigned g_grp_cnt[8 * 32];      // 128B stride per mt-group
__device__ unsigned g_grp_phase[8 * 32];

__device__ __forceinline__ float hsig(float x) {
    return fminf(fmaxf(0.2f * x + 0.5f, 0.0f), 1.0f);
}
__device__ __forceinline__ float ftanh(float x) {
    float t = __expf(-2.0f * fabsf(x));
    return copysignf(__fdividef(1.0f - t, 1.0f + t), x);
}
__device__ __forceinline__ uint32_t smem_u32(const void* p) {
    uint32_t a;
    asm("{ .reg .u64 t; cvta.to.shared.u64 t, %1; cvt.u32.u64 %0, t; }" : "=r"(a) : "l"(p));
    return a;
}

#define LDSM_X4(r0, r1, r2, r3, addr)                                          \
    asm volatile("ldmatrix.sync.aligned.m8n8.x4.shared.b16 {%0,%1,%2,%3}, [%4];" \
                 : "=r"(r0), "=r"(r1), "=r"(r2), "=r"(r3) : "r"(addr))

#define MMA_BF16(d, a0, a1, a2, a3, b0, b1)                                    \
    asm volatile("mma.sync.aligned.m16n8k16.row.col.f32.bf16.bf16.f32 "        \
                 "{%0,%1,%2,%3}, {%4,%5,%6,%7}, {%8,%9}, {%0,%1,%2,%3};"       \
                 : "+f"((d)[0]), "+f"((d)[1]), "+f"((d)[2]), "+f"((d)[3])      \
                 : "r"(a0), "r"(a1), "r"(a2), "r"(a3), "r"(b0), "r"(b1))

#define CP_ASYNC(dst, src, sz) \
    asm volatile("cp.async.cg.shared.global [%0], [%1], 16, %2;" \
                 :: "r"(dst), "l"(src), "r"(sz))
#define CP_COMMIT() asm volatile("cp.async.commit_group;" ::: "memory")
#define CP_WAIT0()  asm volatile("cp.async.wait_group 0;" ::: "memory")
#define CP_WAIT1()  asm volatile("cp.async.wait_group 1;" ::: "memory")
#define CP_WAIT2()  asm volatile("cp.async.wait_group 2;" ::: "memory")
#define CP_WAIT3()  asm volatile("cp.async.wait_group 3;" ::: "memory")

// ---------------- SMEM layout ----------------
#define BROW      1104            // 544*2 + 16B pad
#define SM_BHI    0
#define SM_BLO    105984
#define SM_A      211968          // 4 slab bufs x 4096 (swizzled); red aliases bufs 0-2
#define ABUF_SZ   4096
#define SMEM_TOTAL 228352

// ---------------- prep kernels ----------------
__global__ void reset_bar() {
    if (threadIdx.x < 8 * 32) {
        g_grp_cnt[threadIdx.x] = 0;
        g_grp_phase[threadIdx.x] = 0;
    }
}

__global__ void prep_weights(const float* __restrict__ Wx, const float* __restrict__ Wh) {
    int P = blockIdx.x;                 // P = nt*96 + g*32 + ul
    int nt = P / 96, rq = P - nt * 96;
    int g = rq >> 5, ul = rq & 31;
    int col = g * HH + nt * 32 + ul;
    for (int k = threadIdx.x; k < KTOT; k += blockDim.x) {
        float w = (k < DD) ? Wx[(size_t)k * K3 + col]
                           : Wh[(size_t)(k - DD) * K3 + col];
        __nv_bfloat16 hi = __float2bfloat16(w);
        g_Wp_hi[(size_t)P * KTOT + k] = hi;
        g_Wp_lo[(size_t)P * KTOT + k] = __float2bfloat16(w - __bfloat162float(hi));
    }
}

__global__ void prep_x(const float* __restrict__ x_dyn) {
    int i = blockIdx.x * blockDim.x + threadIdx.x;
    if (i >= BB * TT * DD) return;
    float v = x_dyn[i];
    __nv_bfloat16 hi = __float2bfloat16(v);
    g_x_hi[i] = hi;
    g_x_lo[i] = __float2bfloat16(v - __bfloat162float(hi));
}

// ---------------- split group barrier (16 CTAs per mt) ----------------
// arrive: tid0 only, call AFTER a __syncthreads() covering this CTA's h writes.
__device__ __forceinline__ void grp_arrive(int mt, unsigned round) {
    unsigned old;
    asm volatile("atom.add.acq_rel.gpu.global.u32 %0, [%1], 1;"
                 : "=r"(old) : "l"(&g_grp_cnt[mt * 32]) : "memory");
    if (old + 1u == round * 16u)
        asm volatile("st.release.gpu.global.u32 [%0], %1;"
                     :: "l"(&g_grp_phase[mt * 32]), "r"(round) : "memory");
}
__device__ __forceinline__ void grp_wait(int mt, unsigned round) {
    if (threadIdx.x == 0) {
        unsigned p;
        do {
            asm volatile("ld.acquire.gpu.global.u32 %0, [%1];"
                         : "=r"(p) : "l"(&g_grp_phase[mt * 32]) : "memory");
        } while (p < round);
    }
    __syncthreads();
}

// ---- fragment bank load: 4 A LDSM + 3 B LDSM ----
#define LDSM_BANK(FA, FB, Ab_, Bb_)                                            \
    LDSM_X4(FA[0], FA[1], FA[2], FA[3], (Ab_));                                \
    LDSM_X4(FA[4], FA[5], FA[6], FA[7], (Ab_) + 1024);                         \
    LDSM_X4(FA[8], FA[9], FA[10], FA[11], (Ab_) + 2048);                       \
    LDSM_X4(FA[12], FA[13], FA[14], FA[15], (Ab_) + 3072);                     \
    LDSM_X4(FB[0], FB[1], FB[2], FB[3], bA + (Bb_));                           \
    LDSM_X4(FB[4], FB[5], FB[6], FB[7], bB + (Bb_));                           \
    LDSM_X4(FB[8], FB[9], FB[10], FB[11], bC + (Bb_));

// ---- 18 compensated MMAs on one bank ----
#define MMA_BANK(FA, FB)                                                       \
    MMA_BF16(acc[0][0], FA[0], FA[1], FA[2], FA[3], FB[0], FB[1]);             \
    MMA_BF16(acc[0][1], FA[4], FA[5], FA[6], FA[7], FB[0], FB[1]);             \
    MMA_BF16(acc[1][0], FA[0], FA[1], FA[2], FA[3], FB[2], FB[3]);             \
    MMA_BF16(acc[1][1], FA[4], FA[5], FA[6], FA[7], FB[2], FB[3]);             \
    MMA_BF16(acc[2][0], FA[0], FA[1], FA[2], FA[3], FB[4], FB[5]);             \
    MMA_BF16(acc[2][1], FA[4], FA[5], FA[6], FA[7], FB[4], FB[5]);             \
    MMA_BF16(acc[0][0], FA[0], FA[1], FA[2], FA[3], FB[6], FB[7]);             \
    MMA_BF16(acc[0][1], FA[4], FA[5], FA[6], FA[7], FB[6], FB[7]);             \
    MMA_BF16(acc[1][0], FA[0], FA[1], FA[2], FA[3], FB[8], FB[9]);             \
    MMA_BF16(acc[1][1], FA[4], FA[5], FA[6], FA[7], FB[8], FB[9]);             \
    MMA_BF16(acc[2][0], FA[0], FA[1], FA[2], FA[3], FB[10], FB[11]);           \
    MMA_BF16(acc[2][1], FA[4], FA[5], FA[6], FA[7], FB[10], FB[11]);           \
    MMA_BF16(acc[0][0], FA[8], FA[9], FA[10], FA[11], FB[0], FB[1]);           \
    MMA_BF16(acc[0][1], FA[12], FA[13], FA[14], FA[15], FB[0], FB[1]);         \
    MMA_BF16(acc[1][0], FA[8], FA[9], FA[10], FA[11], FB[2], FB[3]);           \
    MMA_BF16(acc[1][1], FA[12], FA[13], FA[14], FA[15], FB[2], FB[3]);         \
    MMA_BF16(acc[2][0], FA[8], FA[9], FA[10], FA[11], FB[4], FB[5]);           \
    MMA_BF16(acc[2][1], FA[12], FA[13], FA[14], FA[15], FB[4], FB[5]);

// One pipeline iteration: wait -> sync -> issue j+4 -> LDSM j+1 -> MMA j
#define STEP_ITER(J, FAc, FBc, FAn, FBn) do {                                  \
    if ((J) <= 13) { CP_WAIT2(); }                                             \
    else if ((J) == 14) { CP_WAIT1(); }                                        \
    else if ((J) == 15) { CP_WAIT0(); }                                        \
    __syncthreads();                                                           \
    if ((J) <= 12) {                                                           \
        CP_ASYNC(s0 + SM_A + (uint32_t)(((J) + 4) & 3) * ABUF_SZ + dst_off,    \
                 hsrc + hrow + ((uint32_t)((nt + (J) + 3) & 15) << 5), 16);    \
        CP_COMMIT();                                                           \
    }                                                                          \
    if ((J) < 16) {                                                            \
        const uint32_t Ab_ = s0 + SM_A + (uint32_t)(((J) + 1) & 3) * ABUF_SZ + a_off; \
        const uint32_t Bb_ = 64 + 64 * (uint32_t)((nt + (J)) & 15) + khoff;    \
        LDSM_BANK(FAn, FBn, Ab_, Bb_)                                          \
    }                                                                          \
    MMA_BANK(FAc, FBc)                                                         \
} while (0)

// ---------------- persistent LSTM kernel ----------------
// 128 CTAs x 256 thr. CTA tile 32 rows x 32 units (96 z-cols).
// K = 17 slabs of 32 (slab0 = x, slab j = h-block (nt+j-1)&15).
// 4 slab buffers + register double-buffered fragments (R12 schedule).
// Barrier split: arrive posted at end of epilogue; wait-only at step start.
__global__ __launch_bounds__(256, 1)
void lstm_persist(const float* __restrict__ x_static,
                  const float* __restrict__ sk,
                  const float* __restrict__ sb,
                  const float* __restrict__ bias,
                  float* __restrict__ out) {
    extern __shared__ char smem[];
    const uint32_t s0 = smem_u32(smem);
    const int tid = threadIdx.x;
    const int lane = tid & 31;
    const int wid = tid >> 5;
    const int nq = wid & 3;
    const int khalf = wid >> 2;
    const uint32_t khoff = (uint32_t)khalf * 32;
    const int mt = blockIdx.x & 7;
    const int nt = blockIdx.x >> 3;
    const int m0 = mt * 32;
    const int u0 = nt * 32;

    // ---- one-time: weights into SMEM ----
    for (int i = tid; i < 96 * 68; i += 256) {
        int pl = i / 68, c = i - pl * 68;
        size_t src = (size_t)(nt * 96 + pl) * KTOT + c * 8;
        *reinterpret_cast<uint4*>(smem + SM_BHI + pl * BROW + c * 16) =
            *reinterpret_cast<const uint4*>(&g_Wp_hi[src]);
        *reinterpret_cast<uint4*>(smem + SM_BLO + pl * BROW + c * 16) =
            *reinterpret_cast<const uint4*>(&g_Wp_lo[src]);
    }

    // ---- per-thread ownership (epilogue in khalf==0 warps) ----
    const int gr = m0 + (lane >> 2);
    const int uA = u0 + nq * 8 + (lane & 3) * 2;

    const float bf0 = bias[uA],          bf1 = bias[uA + 1];
    const float bg0 = bias[HH + uA],     bg1 = bias[HH + uA + 1];
    const float bo0 = bias[2 * HH + uA], bo1 = bias[2 * HH + uA + 1];

    float c_reg[8], ig_reg[8];
#pragma unroll
    for (int i = 0; i < 8; i++) c_reg[i] = 0.f;
    if (khalf == 0) {
#pragma unroll
        for (int i = 0; i < 4; i++) {
            int row = gr + i * 8;
#pragma unroll
            for (int jj = 0; jj < 2; jj++) {
                int u = uA + jj;
                float a = sb[u];
#pragma unroll
                for (int d = 0; d < DS; d++)
                    a = fmaf(x_static[row * DS + d], sk[d * HH + u], a);
                ig_reg[i * 2 + jj] = hsig(a);
            }
            __nv_bfloat162 z2; z2.x = __float2bfloat16(0.f); z2.y = z2.x;
            *reinterpret_cast<__nv_bfloat162*>(&g_h_hi[0][row * HH + uA]) = z2;
            *reinterpret_cast<__nv_bfloat162*>(&g_h_lo[0][row * HH + uA]) = z2;
        }
    }

    // ---- hoisted loader constants (1 cp.async per thread per slab) ----
    const int halfl = tid >> 7;                 // 0 hi, 1 lo
    const int rowl = (tid >> 2) & 31;
    const int ql = tid & 3;
    const uint32_t dst_off = halfl * 2048 + rowl * 64
                           + ((ql ^ ((rowl >> 1) & 3)) << 4);     // XOR swizzle
    const __nv_bfloat16* __restrict__ xb = halfl ? g_x_lo : g_x_hi;
    const size_t xsrc0 = (size_t)(m0 + rowl) * TT * DD + ql * 8;
    const uint32_t hrow = (m0 + rowl) * HH + ql * 8;              // + b*32

    // ---- ldmatrix lane addresses ----
    const uint32_t a_off = (lane & 15) * 64
        + ((((uint32_t)khalf * 2 + (lane >> 4)) ^ (((lane & 15) >> 1) & 3)) << 4);
    const int oct = lane >> 3, l8 = lane & 7;
    const uint32_t koff = (oct & 1) * 16;
    const int wq8 = nq * 8;
    const uint32_t bA = s0 + SM_BHI + ((oct < 2 ? wq8 : 32 + wq8) + l8) * BROW + koff;
    const uint32_t bB = (oct < 2 ? s0 + SM_BHI + (64 + wq8 + l8) * BROW
                                 : s0 + SM_BLO + (wq8 + l8) * BROW) + koff;
    const uint32_t bC = s0 + SM_BLO + ((oct < 2 ? 32 : 64) + wq8 + l8) * BROW + koff;

    // prologue: h(0) visible within CTA, post arrival, then issue slab0+slab1
    __syncthreads();
    if (tid == 0) grp_arrive(mt, 1u);
    CP_ASYNC(s0 + SM_A + dst_off, xb + xsrc0, 16);
    CP_COMMIT();
    {
        const __nv_bfloat16* hb = halfl ? g_h_lo[0] : g_h_hi[0];
        CP_ASYNC(s0 + SM_A + ABUF_SZ + dst_off, hb + hrow + nt * 32, 16);
        CP_COMMIT();
    }

    uint32_t fA0[16], fB0[12], fA1[16], fB1[12];

#pragma unroll 1
    for (int t = 0; t < TT; t++) {
        const int tpar = t & 1;
        const __nv_bfloat16* __restrict__ hsrc =
            halfl ? g_h_lo[tpar] : g_h_hi[tpar];

        grp_wait(mt, (unsigned)t + 1u);   // all h(t) published group-wide

        // issue slab2 (block (nt+1)&15) and slab3 (block (nt+2)&15)
        CP_ASYNC(s0 + SM_A + 2 * ABUF_SZ + dst_off,
                 hsrc + hrow + (((nt + 1) & 15) << 5), 16);
        CP_COMMIT();
        CP_ASYNC(s0 + SM_A + 3 * ABUF_SZ + dst_off,
                 hsrc + hrow + (((nt + 2) & 15) << 5), 16);
        CP_COMMIT();

        float acc[3][2][4];
#pragma unroll
        for (int g = 0; g < 3; g++)
#pragma unroll
            for (int mf = 0; mf < 2; mf++)
#pragma unroll
                for (int e2 = 0; e2 < 4; e2++) acc[g][mf][e2] = 0.f;

        // preload bank0 <- slab0 (x)
        CP_WAIT3();
        __syncthreads();
        {
            const uint32_t Ab_ = s0 + SM_A + a_off;
            LDSM_BANK(fA0, fB0, Ab_, khoff)
        }

#pragma unroll 1
        for (int j = 0; j < 16; j += 2) {
            STEP_ITER(j,     fA0, fB0, fA1, fB1);
            STEP_ITER(j + 1, fA1, fB1, fA0, fB0);
        }
        STEP_ITER(16, fA0, fB0, fA1, fB1);

        // ---- cross-warp k reduction via smem (aliases slab bufs 0-2) ----
        __syncthreads();
        float* red = reinterpret_cast<float*>(smem + SM_A);
        if (khalf == 1) {
            int s = (wid - 4) * 32 + lane;
#pragma unroll
            for (int g = 0; g < 3; g++)
#pragma unroll
                for (int mf = 0; mf < 2; mf++)
#pragma unroll
                    for (int e2 = 0; e2 < 4; e2++)
                        red[(g * 8 + mf * 4 + e2) * 128 + s] = acc[g][mf][e2];
        }
        __syncthreads();

        if (khalf == 0) {
            int s = wid * 32 + lane;
#pragma unroll
            for (int g = 0; g < 3; g++)
#pragma unroll
                for (int mf = 0; mf < 2; mf++)
#pragma unroll
                    for (int e2 = 0; e2 < 4; e2++)
                        acc[g][mf][e2] += red[(g * 8 + mf * 4 + e2) * 128 + s];

            __nv_bfloat16* __restrict__ hdst_hi = g_h_hi[tpar ^ 1];
            __nv_bfloat16* __restrict__ hdst_lo = g_h_lo[tpar ^ 1];
#pragma unroll
            for (int i = 0; i < 4; i++) {
                const int mf = i >> 1, dp = (i & 1) * 2;
                float zf0 = acc[0][mf][dp + 0] + bf0, zf1 = acc[0][mf][dp + 1] + bf1;
                float zg0 = acc[1][mf][dp + 0] + bg0, zg1 = acc[1][mf][dp + 1] + bg1;
                float zo0 = acc[2][mf][dp + 0] + bo0, zo1 = acc[2][mf][dp + 1] + bo1;
                float c0 = hsig(zf0) * c_reg[i * 2 + 0] + ig_reg[i * 2 + 0] * ftanh(zg0);
                float c1 = hsig(zf1) * c_reg[i * 2 + 1] + ig_reg[i * 2 + 1] * ftanh(zg1);
                c_reg[i * 2 + 0] = c0;
                c_reg[i * 2 + 1] = c1;
                float h0 = hsig(zo0) * ftanh(c0);
                float h1 = hsig(zo1) * ftanh(c1);
                int row = gr + i * 8;
                int idx = row * HH + uA;
                __nv_bfloat16 b0 = __float2bfloat16(h0);
                __nv_bfloat16 b1 = __float2bfloat16(h1);
                __nv_bfloat162 ph; ph.x = b0; ph.y = b1;
                *reinterpret_cast<__nv_bfloat162*>(&hdst_hi[idx]) = ph;
                __nv_bfloat162 pl;
                pl.x = __float2bfloat16(h0 - __bfloat162float(b0));
                pl.y = __float2bfloat16(h1 - __bfloat162float(b1));
                *reinterpret_cast<__nv_bfloat162*>(&hdst_lo[idx]) = pl;
                float2 ov = make_float2(h0, h1);
                *reinterpret_cast<float2*>(&out[(size_t)row * TT * HH + (size_t)t * HH + uA]) = ov;
            }
        }

        __syncthreads();                 // red reads + h(t+1) writes done CTA-wide
        if (tid == 0) grp_arrive(mt, (unsigned)t + 2u);   // publish h(t+1) early
        if (t + 1 < TT) {                // issue next step's slab0 (x) + slab1 (own h)
            CP_ASYNC(s0 + SM_A + dst_off, xb + xsrc0 + (size_t)(t + 1) * DD, 16);
            CP_COMMIT();
            const __nv_bfloat16* hb =
                halfl ? g_h_lo[(t + 1) & 1] : g_h_hi[(t + 1) & 1];
            CP_ASYNC(s0 + SM_A + ABUF_SZ + dst_off, hb + hrow + nt * 32, 16);
            CP_COMMIT();
        }
    }
}

// ---------------- launcher ----------------
extern "C" void kernel_launch(void* const* d_in, const int* in_sizes, int n_in,
                              void* d_out, int out_size) {
    const float* x_dyn    = (const float*)d_in[0];
    const float* x_static = (const float*)d_in[1];
    const float* Wx       = (const float*)d_in[2];
    const float* Wh       = (const float*)d_in[3];
    const float* bias     = (const float*)d_in[4];
    const float* sk       = (const float*)d_in[5];
    const float* sb       = (const float*)d_in[6];
    float* out = (float*)d_out;

    cudaFuncSetAttribute(lstm_persist, cudaFuncAttributeMaxDynamicSharedMemorySize, SMEM_TOTAL);

    reset_bar<<<1, 256>>>();
    prep_weights<<<K3, 128>>>(Wx, Wh);
    prep_x<<<(BB * TT * DD + 127) / 128, 128>>>(x_dyn);
    lstm_persist<<<NBLK, 256, SMEM_TOTAL>>>(x_static, sk, sb, bias, out);
}

// round 15
// speedup vs baseline: 1.4038x; 1.3141x over previous
#include <cuda_runtime.h>
#include <cuda_fp16.h>
#include <math.h>
#include <stdint.h>

#define BB   256
#define TT   365
#define HH   512
#define DD   32
#define K3   1536
#define DS   27
#define NBLK 128
#define KTOT 544

// ---------------- persistent device state ----------------
// Weight staging: row P = nt*96 + g*32 + ul, k in [0,544) = [x(32) ; h(512)]
__device__ __align__(16) __half g_Wp[K3 * KTOT];
__device__ __align__(16) __half g_x[BB * TT * DD];
__device__ __align__(16) __half g_h[2][BB * HH];
__device__ unsigned g_grp_cnt[8 * 32];      // 128B stride per mt-group
__device__ unsigned g_grp_phase[8 * 32];

__device__ __forceinline__ float hsig(float x) {
    return fminf(fmaxf(0.2f * x + 0.5f, 0.0f), 1.0f);
}
__device__ __forceinline__ float ftanh(float x) {
    float t = __expf(-2.0f * fabsf(x));
    return copysignf(__fdividef(1.0f - t, 1.0f + t), x);
}
__device__ __forceinline__ uint32_t smem_u32(const void* p) {
    uint32_t a;
    asm("{ .reg .u64 t; cvta.to.shared.u64 t, %1; cvt.u32.u64 %0, t; }" : "=r"(a) : "l"(p));
    return a;
}

#define LDSM_X4(r0, r1, r2, r3, addr)                                          \
    asm volatile("ldmatrix.sync.aligned.m8n8.x4.shared.b16 {%0,%1,%2,%3}, [%4];" \
                 : "=r"(r0), "=r"(r1), "=r"(r2), "=r"(r3) : "r"(addr))
#define LDSM_X2(r0, r1, addr)                                                  \
    asm volatile("ldmatrix.sync.aligned.m8n8.x2.shared.b16 {%0,%1}, [%2];"     \
                 : "=r"(r0), "=r"(r1) : "r"(addr))

#define MMA_F16(d, a0, a1, a2, a3, b0, b1)                                     \
    asm volatile("mma.sync.aligned.m16n8k16.row.col.f32.f16.f16.f32 "          \
                 "{%0,%1,%2,%3}, {%4,%5,%6,%7}, {%8,%9}, {%0,%1,%2,%3};"       \
                 : "+f"((d)[0]), "+f"((d)[1]), "+f"((d)[2]), "+f"((d)[3])      \
                 : "r"(a0), "r"(a1), "r"(a2), "r"(a3), "r"(b0), "r"(b1))

#define CP_ASYNC8(dst, src) \
    asm volatile("cp.async.ca.shared.global [%0], [%1], 8;" \
                 :: "r"(dst), "l"(src))
#define CP_COMMIT() asm volatile("cp.async.commit_group;" ::: "memory")
#define CP_WAIT0()  asm volatile("cp.async.wait_group 0;" ::: "memory")
#define CP_WAIT1()  asm volatile("cp.async.wait_group 1;" ::: "memory")
#define CP_WAIT2()  asm volatile("cp.async.wait_group 2;" ::: "memory")
#define CP_WAIT3()  asm volatile("cp.async.wait_group 3;" ::: "memory")

// ---------------- SMEM layout ----------------
#define BROW      1104            // 544*2 + 16B pad (conflict-free LDSM phases)
#define SM_B      0               // 96 rows x 1104B = 105984
#define SM_A      105984          // 4 slab bufs x 2048 (swizzled fp16)
#define ABUF_SZ   2048
#define SM_RED    114176          // 24 x 128 floats = 12288
#define SMEM_TOTAL 126464

// ---------------- prep kernels ----------------
__global__ void reset_bar() {
    if (threadIdx.x < 8 * 32) {
        g_grp_cnt[threadIdx.x] = 0;
        g_grp_phase[threadIdx.x] = 0;
    }
}

__global__ void prep_weights(const float* __restrict__ Wx, const float* __restrict__ Wh) {
    int P = blockIdx.x;                 // P = nt*96 + g*32 + ul
    int nt = P / 96, rq = P - nt * 96;
    int g = rq >> 5, ul = rq & 31;
    int col = g * HH + nt * 32 + ul;
    for (int k = threadIdx.x; k < KTOT; k += blockDim.x) {
        float w = (k < DD) ? Wx[(size_t)k * K3 + col]
                           : Wh[(size_t)(k - DD) * K3 + col];
        g_Wp[(size_t)P * KTOT + k] = __float2half_rn(w);
    }
}

__global__ void prep_x(const float* __restrict__ x_dyn) {
    int i = blockIdx.x * blockDim.x + threadIdx.x;
    if (i >= BB * TT * DD) return;
    g_x[i] = __float2half_rn(x_dyn[i]);
}

// ---------------- split group barrier (16 CTAs per mt) ----------------
__device__ __forceinline__ void grp_arrive(int mt, unsigned round) {
    unsigned old;
    asm volatile("atom.add.acq_rel.gpu.global.u32 %0, [%1], 1;"
                 : "=r"(old) : "l"(&g_grp_cnt[mt * 32]) : "memory");
    if (old + 1u == round * 16u)
        asm volatile("st.release.gpu.global.u32 [%0], %1;"
                     :: "l"(&g_grp_phase[mt * 32]), "r"(round) : "memory");
}
__device__ __forceinline__ void grp_wait(int mt, unsigned round) {
    if (threadIdx.x == 0) {
        unsigned p;
        do {
            asm volatile("ld.acquire.gpu.global.u32 %0, [%1];"
                         : "=r"(p) : "l"(&g_grp_phase[mt * 32]) : "memory");
        } while (p < round);
    }
    __syncthreads();
}

// ---- fragment bank load: 2 A x4 + 1 B x4 + 1 B x2 ----
#define LDSM_BANK(FA, FB, Ab_, Bb_)                                            \
    LDSM_X4(FA[0], FA[1], FA[2], FA[3], (Ab_));                                \
    LDSM_X4(FA[4], FA[5], FA[6], FA[7], (Ab_) + 1024);                         \
    LDSM_X4(FB[0], FB[1], FB[2], FB[3], bA + (Bb_));                           \
    LDSM_X2(FB[4], FB[5], bO + (Bb_));

// ---- 6 fp16 MMAs on one bank ----
#define MMA_BANK(FA, FB)                                                       \
    MMA_F16(acc[0][0], FA[0], FA[1], FA[2], FA[3], FB[0], FB[1]);              \
    MMA_F16(acc[0][1], FA[4], FA[5], FA[6], FA[7], FB[0], FB[1]);              \
    MMA_F16(acc[1][0], FA[0], FA[1], FA[2], FA[3], FB[2], FB[3]);              \
    MMA_F16(acc[1][1], FA[4], FA[5], FA[6], FA[7], FB[2], FB[3]);              \
    MMA_F16(acc[2][0], FA[0], FA[1], FA[2], FA[3], FB[4], FB[5]);              \
    MMA_F16(acc[2][1], FA[4], FA[5], FA[6], FA[7], FB[4], FB[5]);

// One pipeline iteration: wait -> sync -> issue j+4 -> LDSM j+1 -> MMA j
#define STEP_ITER(J, FAc, FBc, FAn, FBn) do {                                  \
    if ((J) <= 13) { CP_WAIT2(); }                                             \
    else if ((J) == 14) { CP_WAIT1(); }                                        \
    else if ((J) == 15) { CP_WAIT0(); }                                        \
    __syncthreads();                                                           \
    if ((J) <= 12) {                                                           \
        CP_ASYNC8(s0 + SM_A + (uint32_t)(((J) + 4) & 3) * ABUF_SZ + dst_off,   \
                  hsrc + hrow + ((uint32_t)((nt + (J) + 3) & 15) << 5));       \
        CP_COMMIT();                                                           \
    }                                                                          \
    if ((J) < 16) {                                                            \
        const uint32_t Ab_ = s0 + SM_A + (uint32_t)(((J) + 1) & 3) * ABUF_SZ + a_off; \
        const uint32_t Bb_ = 64 + 64 * (uint32_t)((nt + (J)) & 15) + khoff;    \
        LDSM_BANK(FAn, FBn, Ab_, Bb_)                                          \
    }                                                                          \
    MMA_BANK(FAc, FBc)                                                         \
} while (0)

// ---------------- persistent LSTM kernel ----------------
// 128 CTAs x 256 thr. CTA tile 32 rows x 32 units (96 z-cols).
// K = 17 slabs of 32 (slab0 = x, slab j = h-block (nt+j-1)&15).
// Single-pass fp16 MMA (fp32 accum); R12 pipeline schedule.
__global__ __launch_bounds__(256, 1)
void lstm_persist(const float* __restrict__ x_static,
                  const float* __restrict__ sk,
                  const float* __restrict__ sb,
                  const float* __restrict__ bias,
                  float* __restrict__ out) {
    extern __shared__ char smem[];
    const uint32_t s0 = smem_u32(smem);
    const int tid = threadIdx.x;
    const int lane = tid & 31;
    const int wid = tid >> 5;
    const int nq = wid & 3;
    const int khalf = wid >> 2;
    const uint32_t khoff = (uint32_t)khalf * 32;
    const int mt = blockIdx.x & 7;
    const int nt = blockIdx.x >> 3;
    const int m0 = mt * 32;
    const int u0 = nt * 32;

    // ---- one-time: weights into SMEM (single fp16 copy) ----
    for (int i = tid; i < 96 * 68; i += 256) {
        int pl = i / 68, c = i - pl * 68;
        size_t src = (size_t)(nt * 96 + pl) * KTOT + c * 8;
        *reinterpret_cast<uint4*>(smem + SM_B + pl * BROW + c * 16) =
            *reinterpret_cast<const uint4*>(&g_Wp[src]);
    }

    // ---- per-thread ownership (epilogue in khalf==0 warps) ----
    const int gr = m0 + (lane >> 2);
    const int uA = u0 + nq * 8 + (lane & 3) * 2;

    const float bf0 = bias[uA],          bf1 = bias[uA + 1];
    const float bg0 = bias[HH + uA],     bg1 = bias[HH + uA + 1];
    const float bo0 = bias[2 * HH + uA], bo1 = bias[2 * HH + uA + 1];

    float c_reg[8], ig_reg[8];
#pragma unroll
    for (int i = 0; i < 8; i++) c_reg[i] = 0.f;
    if (khalf == 0) {
#pragma unroll
        for (int i = 0; i < 4; i++) {
            int row = gr + i * 8;
#pragma unroll
            for (int jj = 0; jj < 2; jj++) {
                int u = uA + jj;
                float a = sb[u];
#pragma unroll
                for (int d = 0; d < DS; d++)
                    a = fmaf(x_static[row * DS + d], sk[d * HH + u], a);
                ig_reg[i * 2 + jj] = hsig(a);
            }
            __half2 z2 = __floats2half2_rn(0.f, 0.f);
            *reinterpret_cast<__half2*>(&g_h[0][row * HH + uA]) = z2;
        }
    }

    // ---- hoisted loader constants (1 cp.async 8B per thread per slab) ----
    const int rowl = tid >> 3;                  // 0..31
    const int subl = tid & 7;                   // 8B sub-slot within 64B row
    const int chkl = subl >> 1, winl = subl & 1;
    const uint32_t dst_off = rowl * 64 + ((chkl ^ ((rowl >> 1) & 3)) << 4) + winl * 8;
    const size_t xsrc0 = (size_t)(m0 + rowl) * TT * DD + subl * 4;   // halves
    const uint32_t hrow = (m0 + rowl) * HH + subl * 4;               // + blk*32

    // ---- ldmatrix lane addresses ----
    const uint32_t a_off = (lane & 15) * 64
        + ((((uint32_t)khalf * 2 + (lane >> 4)) ^ (((lane & 15) >> 1) & 3)) << 4);
    const int oct = lane >> 3, l8 = lane & 7;
    const uint32_t koff = (oct & 1) * 16;
    const int wq8 = nq * 8;
    // x4: [f k0, f k8, g k0, g k8]
    const uint32_t bA = s0 + SM_B + ((oct < 2 ? wq8 : 32 + wq8) + l8) * BROW + koff;
    // x2: [o k0, o k8] (lanes 0-15 supply addresses)
    const uint32_t bO = s0 + SM_B + (64 + wq8 + (lane & 7)) * BROW
                      + (((lane & 15) >> 3) << 4);

    // prologue: h(0) visible within CTA, post arrival, issue slab0 (x) + slab1
    __syncthreads();
    if (tid == 0) grp_arrive(mt, 1u);
    CP_ASYNC8(s0 + SM_A + dst_off, g_x + xsrc0);
    CP_COMMIT();
    CP_ASYNC8(s0 + SM_A + ABUF_SZ + dst_off, g_h[0] + hrow + nt * 32);
    CP_COMMIT();

    uint32_t fA0[8], fB0[6], fA1[8], fB1[6];

#pragma unroll 1
    for (int t = 0; t < TT; t++) {
        const int tpar = t & 1;
        const __half* __restrict__ hsrc = g_h[tpar];

        grp_wait(mt, (unsigned)t + 1u);   // all h(t) published group-wide

        // issue slab2 (block (nt+1)&15) and slab3 (block (nt+2)&15)
        CP_ASYNC8(s0 + SM_A + 2 * ABUF_SZ + dst_off,
                  hsrc + hrow + (((nt + 1) & 15) << 5));
        CP_COMMIT();
        CP_ASYNC8(s0 + SM_A + 3 * ABUF_SZ + dst_off,
                  hsrc + hrow + (((nt + 2) & 15) << 5));
        CP_COMMIT();

        float acc[3][2][4];
#pragma unroll
        for (int g = 0; g < 3; g++)
#pragma unroll
            for (int mf = 0; mf < 2; mf++)
#pragma unroll
                for (int e2 = 0; e2 < 4; e2++) acc[g][mf][e2] = 0.f;

        // preload bank0 <- slab0 (x)
        CP_WAIT3();
        __syncthreads();
        {
            const uint32_t Ab_ = s0 + SM_A + a_off;
            LDSM_BANK(fA0, fB0, Ab_, khoff)
        }

#pragma unroll 1
        for (int j = 0; j < 16; j += 2) {
            STEP_ITER(j,     fA0, fB0, fA1, fB1);
            STEP_ITER(j + 1, fA1, fB1, fA0, fB0);
        }
        STEP_ITER(16, fA0, fB0, fA1, fB1);

        // ---- cross-warp k reduction via dedicated smem ----
        __syncthreads();
        float* red = reinterpret_cast<float*>(smem + SM_RED);
        if (khalf == 1) {
            int s = (wid - 4) * 32 + lane;
#pragma unroll
            for (int g = 0; g < 3; g++)
#pragma unroll
                for (int mf = 0; mf < 2; mf++)
#pragma unroll
                    for (int e2 = 0; e2 < 4; e2++)
                        red[(g * 8 + mf * 4 + e2) * 128 + s] = acc[g][mf][e2];
        }
        __syncthreads();

        if (khalf == 0) {
            int s = wid * 32 + lane;
#pragma unroll
            for (int g = 0; g < 3; g++)
#pragma unroll
                for (int mf = 0; mf < 2; mf++)
#pragma unroll
                    for (int e2 = 0; e2 < 4; e2++)
                        acc[g][mf][e2] += red[(g * 8 + mf * 4 + e2) * 128 + s];

            __half* __restrict__ hdst = g_h[tpar ^ 1];
#pragma unroll
            for (int i = 0; i < 4; i++) {
                const int mf = i >> 1, dp = (i & 1) * 2;
                float zf0 = acc[0][mf][dp + 0] + bf0, zf1 = acc[0][mf][dp + 1] + bf1;
                float zg0 = acc[1][mf][dp + 0] + bg0, zg1 = acc[1][mf][dp + 1] + bg1;
                float zo0 = acc[2][mf][dp + 0] + bo0, zo1 = acc[2][mf][dp + 1] + bo1;
                float c0 = hsig(zf0) * c_reg[i * 2 + 0] + ig_reg[i * 2 + 0] * ftanh(zg0);
                float c1 = hsig(zf1) * c_reg[i * 2 + 1] + ig_reg[i * 2 + 1] * ftanh(zg1);
                c_reg[i * 2 + 0] = c0;
                c_reg[i * 2 + 1] = c1;
                float h0 = hsig(zo0) * ftanh(c0);
                float h1 = hsig(zo1) * ftanh(c1);
                int row = gr + i * 8;
                int idx = row * HH + uA;
                *reinterpret_cast<__half2*>(&hdst[idx]) = __floats2half2_rn(h0, h1);
                float2 ov = make_float2(h0, h1);
                *reinterpret_cast<float2*>(&out[(size_t)row * TT * HH + (size_t)t * HH + uA]) = ov;
            }
        }

        __syncthreads();                 // red reads + h(t+1) writes done CTA-wide
        if (tid == 0) grp_arrive(mt, (unsigned)t + 2u);   // publish h(t+1)
        if (t + 1 < TT) {                // issue next step's slab0 (x) + slab1 (own h)
            CP_ASYNC8(s0 + SM_A + dst_off, g_x + xsrc0 + (size_t)(t + 1) * DD);
            CP_COMMIT();
            CP_ASYNC8(s0 + SM_A + ABUF_SZ + dst_off,
                      g_h[(t + 1) & 1] + hrow + nt * 32);
            CP_COMMIT();
        }
    }
}

// ---------------- launcher ----------------
extern "C" void kernel_launch(void* const* d_in, const int* in_sizes, int n_in,
                              void* d_out, int out_size) {
    const float* x_dyn    = (const float*)d_in[0];
    const float* x_static = (const float*)d_in[1];
    const float* Wx       = (const float*)d_in[2];
    const float* Wh       = (const float*)d_in[3];
    const float* bias     = (const float*)d_in[4];
    const float* sk       = (const float*)d_in[5];
    const float* sb       = (const float*)d_in[6];
    float* out = (float*)d_out;

    cudaFuncSetAttribute(lstm_persist, cudaFuncAttributeMaxDynamicSharedMemorySize, SMEM_TOTAL);

    reset_bar<<<1, 256>>>();
    prep_weights<<<K3, 128>>>(Wx, Wh);
    prep_x<<<(BB * TT * DD + 127) / 128, 128>>>(x_dyn);
    lstm_persist<<<NBLK, 256, SMEM_TOTAL>>>(x_static, sk, sb, bias, out);
}

// round 16
// speedup vs baseline: 1.6225x; 1.1558x over previous
#include <cuda_runtime.h>
#include <cuda_fp16.h>
#include <math.h>
#include <stdint.h>

#define BB   256
#define TT   365
#define HH   512
#define DD   32
#define K3   1536
#define DS   27
#define NBLK 128
#define KTOT 544

// ---------------- persistent device state ----------------
// Weight staging: row P = nt*96 + g*32 + ul, k in [0,544) = [x(32) ; h(512)]
__device__ __align__(16) __half g_Wp[K3 * KTOT];
__device__ __align__(16) __half g_x[BB * TT * DD];
__device__ __align__(16) __half g_h[2][BB * HH];
__device__ unsigned g_grp_cnt[8 * 32];      // 128B stride per mt-group
__device__ unsigned g_grp_phase[8 * 32];

__device__ __forceinline__ float hsig(float x) {
    return fminf(fmaxf(0.2f * x + 0.5f, 0.0f), 1.0f);
}
__device__ __forceinline__ float ftanh(float x) {
    float t = __expf(-2.0f * fabsf(x));
    return copysignf(__fdividef(1.0f - t, 1.0f + t), x);
}
__device__ __forceinline__ uint32_t smem_u32(const void* p) {
    uint32_t a;
    asm("{ .reg .u64 t; cvta.to.shared.u64 t, %1; cvt.u32.u64 %0, t; }" : "=r"(a) : "l"(p));
    return a;
}

#define LDSM_X4(r0, r1, r2, r3, addr)                                          \
    asm volatile("ldmatrix.sync.aligned.m8n8.x4.shared.b16 {%0,%1,%2,%3}, [%4];" \
                 : "=r"(r0), "=r"(r1), "=r"(r2), "=r"(r3) : "r"(addr))
#define LDSM_X2(r0, r1, addr)                                                  \
    asm volatile("ldmatrix.sync.aligned.m8n8.x2.shared.b16 {%0,%1}, [%2];"     \
                 : "=r"(r0), "=r"(r1) : "r"(addr))

#define MMA_F16(d, a0, a1, a2, a3, b0, b1)                                     \
    asm volatile("mma.sync.aligned.m16n8k16.row.col.f32.f16.f16.f32 "          \
                 "{%0,%1,%2,%3}, {%4,%5,%6,%7}, {%8,%9}, {%0,%1,%2,%3};"       \
                 : "+f"((d)[0]), "+f"((d)[1]), "+f"((d)[2]), "+f"((d)[3])      \
                 : "r"(a0), "r"(a1), "r"(a2), "r"(a3), "r"(b0), "r"(b1))

#define CP_ASYNC16(dst, src) \
    asm volatile("cp.async.cg.shared.global [%0], [%1], 16;" \
                 :: "r"(dst), "l"(src))
#define CP_COMMIT() asm volatile("cp.async.commit_group;" ::: "memory")
#define CP_WAIT0()  asm volatile("cp.async.wait_group 0;" ::: "memory")
#define CP_WAIT1()  asm volatile("cp.async.wait_group 1;" ::: "memory")
#define CP_WAIT2()  asm volatile("cp.async.wait_group 2;" ::: "memory")

// ---------------- SMEM layout ----------------
#define BROW      1104            // 544*2 + 16B pad (conflict-free LDSM phases)
#define SM_B      0               // 96 rows x 1104B = 105984
#define SM_A      105984          // 4 chunk bufs x 4096 (64-k fp16, swizzled)
#define ABUF_SZ   4096
#define SM_RED    122368          // 24 x 128 floats = 12288
#define SMEM_TOTAL 134656

// ---------------- prep kernels ----------------
__global__ void reset_bar() {
    if (threadIdx.x < 8 * 32) {
        g_grp_cnt[threadIdx.x] = 0;
        g_grp_phase[threadIdx.x] = 0;
    }
}

__global__ void prep_weights(const float* __restrict__ Wx, const float* __restrict__ Wh) {
    int P = blockIdx.x;                 // P = nt*96 + g*32 + ul
    int nt = P / 96, rq = P - nt * 96;
    int g = rq >> 5, ul = rq & 31;
    int col = g * HH + nt * 32 + ul;
    for (int k = threadIdx.x; k < KTOT; k += blockDim.x) {
        float w = (k < DD) ? Wx[(size_t)k * K3 + col]
                           : Wh[(size_t)(k - DD) * K3 + col];
        g_Wp[(size_t)P * KTOT + k] = __float2half_rn(w);
    }
}

__global__ void prep_x(const float* __restrict__ x_dyn) {
    int i = blockIdx.x * blockDim.x + threadIdx.x;
    if (i >= BB * TT * DD) return;
    g_x[i] = __float2half_rn(x_dyn[i]);
}

// ---------------- split group barrier (16 CTAs per mt) ----------------
__device__ __forceinline__ void grp_arrive(int mt, unsigned round) {
    unsigned old;
    asm volatile("atom.add.acq_rel.gpu.global.u32 %0, [%1], 1;"
                 : "=r"(old) : "l"(&g_grp_cnt[mt * 32]) : "memory");
    if (old + 1u == round * 16u)
        asm volatile("st.release.gpu.global.u32 [%0], %1;"
                     :: "l"(&g_grp_phase[mt * 32]), "r"(round) : "memory");
}
__device__ __forceinline__ void grp_wait(int mt, unsigned round) {
    if (threadIdx.x == 0) {
        unsigned p;
        do {
            asm volatile("ld.acquire.gpu.global.u32 %0, [%1];"
                         : "=r"(p) : "l"(&g_grp_phase[mt * 32]) : "memory");
        } while (p < round);
    }
    __syncthreads();
}

// ---- fragment bank load for one 64-k chunk (this warp's 2 ks) ----
#define LDSM_BANK(FA, FB, Bu_, Bb_)                                            \
    LDSM_X4(FA[0], FA[1], FA[2], FA[3], (Bu_) + aof00);                        \
    LDSM_X4(FA[4], FA[5], FA[6], FA[7], (Bu_) + aof10);                        \
    LDSM_X4(FA[8], FA[9], FA[10], FA[11], (Bu_) + aof01);                      \
    LDSM_X4(FA[12], FA[13], FA[14], FA[15], (Bu_) + aof11);                    \
    LDSM_X4(FB[0], FB[1], FB[2], FB[3], bA + (Bb_));                           \
    LDSM_X2(FB[4], FB[5], bO + (Bb_));                                         \
    LDSM_X4(FB[6], FB[7], FB[8], FB[9], bA + (Bb_) + 32);                      \
    LDSM_X2(FB[10], FB[11], bO + (Bb_) + 32);

// ---- 12 fp16 MMAs on one bank (2 ks x 6) ----
#define MMA_BANK(FA, FB)                                                       \
    MMA_F16(acc[0][0], FA[0], FA[1], FA[2], FA[3], FB[0], FB[1]);              \
    MMA_F16(acc[0][1], FA[4], FA[5], FA[6], FA[7], FB[0], FB[1]);              \
    MMA_F16(acc[1][0], FA[0], FA[1], FA[2], FA[3], FB[2], FB[3]);              \
    MMA_F16(acc[1][1], FA[4], FA[5], FA[6], FA[7], FB[2], FB[3]);              \
    MMA_F16(acc[2][0], FA[0], FA[1], FA[2], FA[3], FB[4], FB[5]);              \
    MMA_F16(acc[2][1], FA[4], FA[5], FA[6], FA[7], FB[4], FB[5]);              \
    MMA_F16(acc[0][0], FA[8], FA[9], FA[10], FA[11], FB[6], FB[7]);            \
    MMA_F16(acc[0][1], FA[12], FA[13], FA[14], FA[15], FB[6], FB[7]);          \
    MMA_F16(acc[1][0], FA[8], FA[9], FA[10], FA[11], FB[8], FB[9]);            \
    MMA_F16(acc[1][1], FA[12], FA[13], FA[14], FA[15], FB[8], FB[9]);          \
    MMA_F16(acc[2][0], FA[8], FA[9], FA[10], FA[11], FB[10], FB[11]);          \
    MMA_F16(acc[2][1], FA[12], FA[13], FA[14], FA[15], FB[10], FB[11]);

// One pipeline iteration (J = 0..7):
// wait chunk J+1 landed -> sync -> issue chunk J+3 -> LDSM J+1 -> MMA J
#define STEP_ITER(J, FAc, FBc, FAn, FBn) do {                                  \
    if ((J) <= 6) { CP_WAIT1(); } else { CP_WAIT0(); }                         \
    __syncthreads();                                                           \
    if ((J) <= 5) {                                                            \
        CP_ASYNC16(s0 + SM_A + (uint32_t)(((J) + 3) & 3) * ABUF_SZ + dst_off,  \
                   hsrc + hrow + ((uint32_t)((blkbase + 2 * ((J) + 3)) & 15) << 5)); \
        CP_COMMIT();                                                           \
    }                                                                          \
    {                                                                          \
        const uint32_t Bu_ = s0 + SM_A + (uint32_t)(((J) + 1) & 3) * ABUF_SZ;  \
        const uint32_t Bb_ = 64u +                                             \
            ((uint32_t)((nt + 2 * ((J) + 1) + khalf - 1) & 15) << 6);          \
        LDSM_BANK(FAn, FBn, Bu_, Bb_)                                          \
    }                                                                          \
    MMA_BANK(FAc, FBc)                                                         \
} while (0)

// ---------------- persistent LSTM kernel ----------------
// 128 CTAs x 256 thr. CTA tile 32 rows x 32 units (96 z-cols).
// K = 9 chunks of 64 (chunk0 = x + own h-block; chunks 1-7 = 2 h-blocks;
// chunk8 = last h-block + dummy upper half skipped by khalf1).
// 4 chunk buffers + register double-buffered fragments; single-pass fp16.
__global__ __launch_bounds__(256, 1)
void lstm_persist(const float* __restrict__ x_static,
                  const float* __restrict__ sk,
                  const float* __restrict__ sb,
                  const float* __restrict__ bias,
                  float* __restrict__ out) {
    extern __shared__ char smem[];
    const uint32_t s0 = smem_u32(smem);
    const int tid = threadIdx.x;
    const int lane = tid & 31;
    const int wid = tid >> 5;
    const int nq = wid & 3;
    const int khalf = wid >> 2;
    const int mt = blockIdx.x & 7;
    const int nt = blockIdx.x >> 3;
    const int m0 = mt * 32;
    const int u0 = nt * 32;

    // ---- one-time: weights into SMEM ----
    for (int i = tid; i < 96 * 68; i += 256) {
        int pl = i / 68, c = i - pl * 68;
        size_t src = (size_t)(nt * 96 + pl) * KTOT + c * 8;
        *reinterpret_cast<uint4*>(smem + SM_B + pl * BROW + c * 16) =
            *reinterpret_cast<const uint4*>(&g_Wp[src]);
    }

    // ---- per-thread ownership (epilogue in khalf==0 warps) ----
    const int gr = m0 + (lane >> 2);
    const int uA = u0 + nq * 8 + (lane & 3) * 2;

    const float bf0 = bias[uA],          bf1 = bias[uA + 1];
    const float bg0 = bias[HH + uA],     bg1 = bias[HH + uA + 1];
    const float bo0 = bias[2 * HH + uA], bo1 = bias[2 * HH + uA + 1];

    float c_reg[8], ig_reg[8];
#pragma unroll
    for (int i = 0; i < 8; i++) c_reg[i] = 0.f;
    if (khalf == 0) {
#pragma unroll
        for (int i = 0; i < 4; i++) {
            int row = gr + i * 8;
#pragma unroll
            for (int jj = 0; jj < 2; jj++) {
                int u = uA + jj;
                float a = sb[u];
#pragma unroll
                for (int d = 0; d < DS; d++)
                    a = fmaf(x_static[row * DS + d], sk[d * HH + u], a);
                ig_reg[i * 2 + jj] = hsig(a);
            }
            *reinterpret_cast<__half2*>(&g_h[0][row * HH + uA]) =
                __floats2half2_rn(0.f, 0.f);
        }
    }

    // ---- hoisted loader constants (1 cp.async 16B per thread per chunk) ----
    const int rowl = tid >> 3;                  // 0..31
    const int subl = tid & 7;                   // 16B slot within 128B row
    const int sL = subl >> 2;                   // slab half within chunk
    const uint32_t dst_off = rowl * 128 + ((subl ^ (rowl & 7)) << 4);
    const size_t xsrc0 = (size_t)(m0 + rowl) * TT * DD + (subl & 3) * 8;
    const uint32_t hrow = (m0 + rowl) * HH + (subl & 3) * 8;      // + blk*32
    const int blkbase = nt + 15 + sL;           // chunk c: blk = (blkbase+2c)&15

    // ---- ldmatrix lane addresses ----
    // A: 128B rows, 16B-chunk XOR swizzle; per (mfrag, ks-sub) constants
    uint32_t aof00, aof01, aof10, aof11;
    {
        const int r0 = lane & 15, r1 = 16 + (lane & 15);
        const int colh = lane >> 4;
        const int cb = khalf * 4 + colh;
#define AOFF(r, c) ((uint32_t)((r) * 128 + ((((c)) ^ ((r) & 7)) << 4)))
        aof00 = AOFF(r0, cb);     aof01 = AOFF(r0, cb + 2);
        aof10 = AOFF(r1, cb);     aof11 = AOFF(r1, cb + 2);
#undef AOFF
    }
    const int oct = lane >> 3, l8 = lane & 7;
    const uint32_t koff = (oct & 1) * 16;
    const int wq8 = nq * 8;
    // x4: [f k0, f k8, g k0, g k8]
    const uint32_t bA = s0 + SM_B + ((oct < 2 ? wq8 : 32 + wq8) + l8) * BROW + koff;
    // x2: [o k0, o k8] (lanes 0-15 supply addresses)
    const uint32_t bO = s0 + SM_B + (64 + wq8 + (lane & 7)) * BROW
                      + (((lane & 15) >> 3) << 4);

    // prologue: h(0) visible within CTA, post arrival, issue chunk0 (x + own h)
    __syncthreads();
    if (tid == 0) grp_arrive(mt, 1u);
    {
        const __half* src0 = (sL == 0) ? (g_x + xsrc0)
                                       : (g_h[0] + hrow + ((uint32_t)nt << 5));
        CP_ASYNC16(s0 + SM_A + dst_off, src0);
        CP_COMMIT();
    }

    uint32_t fA0[16], fB0[12], fA1[16], fB1[12];

#pragma unroll 1
    for (int t = 0; t < TT; t++) {
        const int tpar = t & 1;
        const __half* __restrict__ hsrc = g_h[tpar];

        grp_wait(mt, (unsigned)t + 1u);   // all h(t) published group-wide

        // issue chunk1 (blocks nt+1+sL) and chunk2 (blocks nt+3+sL)
        CP_ASYNC16(s0 + SM_A + 1 * ABUF_SZ + dst_off,
                   hsrc + hrow + ((uint32_t)((blkbase + 2) & 15) << 5));
        CP_COMMIT();
        CP_ASYNC16(s0 + SM_A + 2 * ABUF_SZ + dst_off,
                   hsrc + hrow + ((uint32_t)((blkbase + 4) & 15) << 5));
        CP_COMMIT();

        float acc[3][2][4];
#pragma unroll
        for (int g = 0; g < 3; g++)
#pragma unroll
            for (int mf = 0; mf < 2; mf++)
#pragma unroll
                for (int e2 = 0; e2 < 4; e2++) acc[g][mf][e2] = 0.f;

        // preload bank0 <- chunk0
        CP_WAIT2();
        __syncthreads();
        {
            const uint32_t Bb0 = khalf ? (64u + ((uint32_t)nt << 6)) : 0u;
            LDSM_BANK(fA0, fB0, s0 + SM_A, Bb0)
        }

        STEP_ITER(0, fA0, fB0, fA1, fB1);
        STEP_ITER(1, fA1, fB1, fA0, fB0);
        STEP_ITER(2, fA0, fB0, fA1, fB1);
        STEP_ITER(3, fA1, fB1, fA0, fB0);
        STEP_ITER(4, fA0, fB0, fA1, fB1);
        STEP_ITER(5, fA1, fB1, fA0, fB0);
        STEP_ITER(6, fA0, fB0, fA1, fB1);
        STEP_ITER(7, fA1, fB1, fA0, fB0);
        // chunk8: only lower half is real (slab16); khalf1 skips
        if (khalf == 0) { MMA_BANK(fA0, fB0) }

        // ---- cross-warp k reduction via dedicated smem ----
        float* red = reinterpret_cast<float*>(smem + SM_RED);
        if (khalf == 1) {
            int s = (wid - 4) * 32 + lane;
#pragma unroll
            for (int g = 0; g < 3; g++)
#pragma unroll
                for (int mf = 0; mf < 2; mf++)
#pragma unroll
                    for (int e2 = 0; e2 < 4; e2++)
                        red[(g * 8 + mf * 4 + e2) * 128 + s] = acc[g][mf][e2];
        }
        __syncthreads();

        if (khalf == 0) {
            int s = wid * 32 + lane;
#pragma unroll
            for (int g = 0; g < 3; g++)
#pragma unroll
                for (int mf = 0; mf < 2; mf++)
#pragma unroll
                    for (int e2 = 0; e2 < 4; e2++)
                        acc[g][mf][e2] += red[(g * 8 + mf * 4 + e2) * 128 + s];

            __half* __restrict__ hdst = g_h[tpar ^ 1];
#pragma unroll
            for (int i = 0; i < 4; i++) {
                const int mf = i >> 1, dp = (i & 1) * 2;
                float zf0 = acc[0][mf][dp + 0] + bf0, zf1 = acc[0][mf][dp + 1] + bf1;
                float zg0 = acc[1][mf][dp + 0] + bg0, zg1 = acc[1][mf][dp + 1] + bg1;
                float zo0 = acc[2][mf][dp + 0] + bo0, zo1 = acc[2][mf][dp + 1] + bo1;
                float c0 = hsig(zf0) * c_reg[i * 2 + 0] + ig_reg[i * 2 + 0] * ftanh(zg0);
                float c1 = hsig(zf1) * c_reg[i * 2 + 1] + ig_reg[i * 2 + 1] * ftanh(zg1);
                c_reg[i * 2 + 0] = c0;
                c_reg[i * 2 + 1] = c1;
                float h0 = hsig(zo0) * ftanh(c0);
                float h1 = hsig(zo1) * ftanh(c1);
                int row = gr + i * 8;
                int idx = row * HH + uA;
                *reinterpret_cast<__half2*>(&hdst[idx]) = __floats2half2_rn(h0, h1);
                float2 ov = make_float2(h0, h1);
                *reinterpret_cast<float2*>(&out[(size_t)row * TT * HH + (size_t)t * HH + uA]) = ov;
            }
        }

        __syncthreads();                 // red reads + h(t+1) writes done CTA-wide
        if (tid == 0) grp_arrive(mt, (unsigned)t + 2u);   // publish h(t+1)
        if (t + 1 < TT) {                // issue next step's chunk0 (x + own h)
            const __half* src0 = (sL == 0)
                ? (g_x + xsrc0 + (size_t)(t + 1) * DD)
                : (g_h[(t + 1) & 1] + hrow + ((uint32_t)nt << 5));
            CP_ASYNC16(s0 + SM_A + dst_off, src0);
            CP_COMMIT();
        }
    }
}

// ---------------- launcher ----------------
extern "C" void kernel_launch(void* const* d_in, const int* in_sizes, int n_in,
                              void* d_out, int out_size) {
    const float* x_dyn    = (const float*)d_in[0];
    const float* x_static = (const float*)d_in[1];
    const float* Wx       = (const float*)d_in[2];
    const float* Wh       = (const float*)d_in[3];
    const float* bias     = (const float*)d_in[4];
    const float* sk       = (const float*)d_in[5];
    const float* sb       = (const float*)d_in[6];
    float* out = (float*)d_out;

    cudaFuncSetAttribute(lstm_persist, cudaFuncAttributeMaxDynamicSharedMemorySize, SMEM_TOTAL);

    reset_bar<<<1, 256>>>();
    prep_weights<<<K3, 128>>>(Wx, Wh);
    prep_x<<<(BB * TT * DD + 127) / 128, 128>>>(x_dyn);
    lstm_persist<<<NBLK, 256, SMEM_TOTAL>>>(x_static, sk, sb, bias, out);
}